// round 11
// baseline (speedup 1.0000x reference)
#include <cuda_runtime.h>
#include <cuda_fp16.h>
#include <math.h>
#include <stdint.h>

// ---------------------------------------------------------------------------
// Problem constants
// ---------------------------------------------------------------------------
#define NROWS 4096          // B*SLEN
#define DIM   512
#define MS    (4096*512)
#define NHEAD 8
#define DH    64
#define SLEN  1024
#define EPSLN 1e-6f

// ---------------------------------------------------------------------------
// Device-resident input pointer table + route table
// ---------------------------------------------------------------------------
struct Ptrs {
    const float *inpute, *inputo, *node_p, *edge_p;
    const float *edge_W, *edge_b, *edge_g, *edge_beta;
    const float *node_W, *node_b, *node_g, *node_beta;
    const float *out_g, *out_beta;
};
__device__ Ptrs g_ptrs;

struct NR {
    int act; float aw;
    int q_in, q_op, q_e; float q_w;
    int k_valid, k_in, k_op, k_e; float k_w;
    int v_valid, v_in, v_op, v_e; float v_w;
};
__device__ NR  g_nr[8];
__device__ int g_processed[8];

// ---------------------------------------------------------------------------
// Scratch
// ---------------------------------------------------------------------------
__device__ float g_outs[8 * MS];
__device__ float g_qv[MS], g_kv[MS], g_vv[MS];
__device__ float g_h0[MS], g_h1[MS], g_h2[MS];
__device__ __align__(16) __half g_EXh[3 * MS], g_EXl[3 * MS];   // edge GEMM A inputs (hi/lo fp16)
__device__ __align__(16) __half g_NXh[3 * MS], g_NXl[3 * MS];   // node GEMM A inputs
__device__ __align__(16) __half g_Wt[8 * 7 * DIM * DIM];        // W^T single fp16 [node][slot][n][k]

// ---------------------------------------------------------------------------
// Helpers
// ---------------------------------------------------------------------------
__device__ __forceinline__ const float* buf_in(int idx) {
    if (idx == 0) return g_ptrs.inpute;
    if (idx == 1) return g_ptrs.inputo;
    return g_outs + (size_t)(idx - 2) * MS;
}

__device__ __forceinline__ float geluf(float x) {
    float x3 = x * x * x;
    return 0.5f * x * (1.0f + tanhf(0.7978845608028654f * (x + 0.044715f * x3)));
}
__device__ __forceinline__ float sigmoidf_(float x) {
    return 1.0f / (1.0f + expf(-x));
}

__device__ __forceinline__ float wsum(float v) {
#pragma unroll
    for (int o = 16; o; o >>= 1) v += __shfl_xor_sync(0xffffffffu, v, o);
    return v;
}

__device__ __forceinline__ void split_h(float v, __half& h, __half& l) {
    h = __float2half_rn(v);
    l = __float2half_rn(v - __half2float(h));
}

// ---------------------------------------------------------------------------
// mma.sync / ldmatrix / cp.async helpers
// ---------------------------------------------------------------------------
__device__ __forceinline__ uint32_t smem_u32(const void* p) {
    uint32_t a;
    asm("{ .reg .u64 t; cvta.to.shared.u64 t, %1; cvt.u32.u64 %0, t; }" : "=r"(a) : "l"(p));
    return a;
}
__device__ __forceinline__ void ldm4(uint32_t addr, uint32_t r[4]) {
    asm volatile("ldmatrix.sync.aligned.m8n8.x4.shared.b16 {%0,%1,%2,%3}, [%4];"
                 : "=r"(r[0]), "=r"(r[1]), "=r"(r[2]), "=r"(r[3]) : "r"(addr));
}
__device__ __forceinline__ void ldm4t(uint32_t addr, uint32_t r[4]) {
    asm volatile("ldmatrix.sync.aligned.m8n8.x4.trans.shared.b16 {%0,%1,%2,%3}, [%4];"
                 : "=r"(r[0]), "=r"(r[1]), "=r"(r[2]), "=r"(r[3]) : "r"(addr));
}
__device__ __forceinline__ void mma16816(float c[4], const uint32_t a[4],
                                         uint32_t b0, uint32_t b1) {
    asm volatile(
        "mma.sync.aligned.m16n8k16.row.col.f32.f16.f16.f32 "
        "{%0,%1,%2,%3}, {%4,%5,%6,%7}, {%8,%9}, {%0,%1,%2,%3};"
        : "+f"(c[0]), "+f"(c[1]), "+f"(c[2]), "+f"(c[3])
        : "r"(a[0]), "r"(a[1]), "r"(a[2]), "r"(a[3]), "r"(b0), "r"(b1));
}
// fp16-accumulator variant (used for the low-order product; its contribution is
// ~2^-11 of the result, so fp16 accumulation error is negligible)
__device__ __forceinline__ void mma16816h(uint32_t c[2], const uint32_t a[4],
                                          uint32_t b0, uint32_t b1) {
    asm volatile(
        "mma.sync.aligned.m16n8k16.row.col.f16.f16.f16.f16 "
        "{%0,%1}, {%2,%3,%4,%5}, {%6,%7}, {%0,%1};"
        : "+r"(c[0]), "+r"(c[1])
        : "r"(a[0]), "r"(a[1]), "r"(a[2]), "r"(a[3]), "r"(b0), "r"(b1));
}
__device__ __forceinline__ void cpa16(uint32_t dst, const void* src) {
    asm volatile("cp.async.ca.shared.global [%0], [%1], 16;" :: "r"(dst), "l"(src));
}
#define CPA_COMMIT() asm volatile("cp.async.commit_group;" ::: "memory")
#define CPA_WAIT2()  asm volatile("cp.async.wait_group 2;" ::: "memory")

#define SW128(o) ((o) ^ (((o) >> 3) & 0x70))

__device__ __forceinline__ uint32_t pack_h2(float x, float y) {
    __half2 h = __float22half2_rn(make_float2(x, y));
    return *(uint32_t*)&h;
}
__device__ __forceinline__ void cvt_hilo(float4 v, uint2& hi, uint2& lo) {
    hi = make_uint2(pack_h2(v.x, v.y), pack_h2(v.z, v.w));
    __half2 h0 = *(__half2*)&hi.x;
    __half2 h1 = *(__half2*)&hi.y;
    float lx = v.x - __half2float(h0.x);
    float ly = v.y - __half2float(h0.y);
    float lz = v.z - __half2float(h1.x);
    float lw = v.w - __half2float(h1.y);
    lo = make_uint2(pack_h2(lx, ly), pack_h2(lz, lw));
}
__device__ __forceinline__ uint2 cvt_h(float4 v) {
    return make_uint2(pack_h2(v.x, v.y), pack_h2(v.z, v.w));
}

// ---------------------------------------------------------------------------
// Setup + routing
// ---------------------------------------------------------------------------
__global__ void setup_k(const float* a0, const float* a1, const float* a2, const float* a3,
                        const float* a4, const float* a5, const float* a6, const float* a7,
                        const float* a8, const float* a9, const float* a10, const float* a11,
                        const float* a12, const float* a13) {
    Ptrs p;
    p.inpute = a0; p.inputo = a1; p.node_p = a2; p.edge_p = a3;
    p.edge_W = a4; p.edge_b = a5; p.edge_g = a6; p.edge_beta = a7;
    p.node_W = a8; p.node_b = a9; p.node_g = a10; p.node_beta = a11;
    p.out_g = a12; p.out_beta = a13;
    g_ptrs = p;
}

__device__ int d_amax(const float* x, int n, int lo) {
    int bi = lo; float bv = x[lo];
    for (int i = lo + 1; i < n; i++) { if (x[i] > bv) { bv = x[i]; bi = i; } }
    return bi;
}
__device__ float d_smw(const float* x, int n, int lo, int sel) {
    float mx = x[lo];
    for (int i = lo + 1; i < n; i++) mx = fmaxf(mx, x[i]);
    float s = 0.f;
    for (int i = lo; i < n; i++) s += expf(x[i] - mx);
    return expf(x[sel] - mx) / s;
}

__global__ void routing_k() {
    if (threadIdx.x || blockIdx.x) return;
    const float* np = g_ptrs.node_p;
    const float* ep = g_ptrs.edge_p;
    for (int i = 0; i < 8; i++) g_processed[i] = 0;
    int lind = 0;
    for (int c = 0; c < 8; c++) {
        int nsrc = (c + 2 < 5) ? c + 2 : 5;
        int snode = c - nsrc;
        int n = nsrc * 5;
        const float* e0 = ep + 0 * 170 + lind * 5;
        const float* e1 = ep + 1 * 170 + lind * 5;
        const float* e2 = ep + 2 * 170 + lind * 5;
        NR r; r.k_valid = 0; r.v_valid = 0;
        r.k_in = 0; r.k_op = 4; r.k_e = 0; r.k_w = 0.f;
        r.v_in = 0; r.v_op = 4; r.v_e = 0; r.v_w = 0.f;

        int nact = d_amax(np + c * 8, 8, 0);
        r.act = nact;
        r.aw = d_smw(np + c * 8, 8, 0, nact);

        int qs = d_amax(e0, n, 5);
        int qse = qs / 5;
        r.q_in = (qse == 0) ? 0 : (snode + qse + 2);
        r.q_op = qs % 5; r.q_e = lind + qse;
        r.q_w = d_smw(e0, n, 5, qs);
        if (r.q_in >= 2) g_processed[r.q_in - 2] = 1;

        if (nact < 7) {
            int lo = (nact > 0) ? 5 : 0;
            int ks = d_amax(e1, n, lo);
            int kse = ks / 5;
            r.k_valid = 1;
            r.k_in = (kse == 0) ? 0 : (snode + kse + 2);
            r.k_op = ks % 5; r.k_e = lind + kse;
            r.k_w = d_smw(e1, n, lo, ks);
            if (r.k_in >= 2) g_processed[r.k_in - 2] = 1;
            int ktype = (kse == 0) ? -2 : -1;
            if (nact < 5) {
                r.v_valid = 1;
                int vs, vlo, vn;
                if (nact == 0 && ktype == -2) { vlo = 0; vn = 5; }
                else if (nact > 0)            { vlo = 5; vn = n; }
                else                          { vlo = 0; vn = n; }
                vs = d_amax(e2, vn, vlo);
                int vse = vs / 5;
                r.v_in = (vse == 0) ? 0 : (snode + vse + 2);
                r.v_op = vs % 5; r.v_e = lind + vse;
                r.v_w = d_smw(e2, vn, vlo, vs);
                if (r.v_in >= 2) g_processed[r.v_in - 2] = 1;
            }
        }
        g_nr[c] = r;
        lind += nsrc;
    }
}

// role r output feeds node GEMM slot 3+r?
__device__ __forceinline__ bool need_hilo_role(int act, int role) {
    if (role == 0) return act == 1 || act == 3;
    if (role == 1) return act == 0 || act == 1 || act == 3 || act == 5;
    return act == 0 || act == 3;
}

// ---------------------------------------------------------------------------
// Weight selection for slot 0..6
// ---------------------------------------------------------------------------
__device__ const float* resolve_w(int node, int slot) {
    NR r = g_nr[node];
    if (slot < 3) {
        int valid, op, e;
        if (slot == 0)      { valid = 1;         op = r.q_op; e = r.q_e; }
        else if (slot == 1) { valid = r.k_valid; op = r.k_op; e = r.k_e; }
        else                { valid = r.v_valid; op = r.v_op; e = r.v_e; }
        if (valid && op <= 3) return g_ptrs.edge_W + (size_t)e * DIM * DIM;
        return nullptr;
    }
    int a = r.act, j = slot - 3;
    bool need =
        (j == 0 && (a == 0 || a == 1 || a == 3)) ||
        (j == 1 && (a == 0 || a == 1 || a == 3 || a == 5)) ||
        (j == 2 && (a == 0 || a == 3)) ||
        (j == 3 && (a == 0 || a == 1 || a == 3));
    if (need) return g_ptrs.node_W + ((size_t)node * 4 + j) * DIM * DIM;
    return nullptr;
}

// Convert+transpose W -> single fp16.  grid (16,16,56) block (32,8)
__global__ void conv_w_all() {
    int z = blockIdx.z; int node = z / 7, slot = z % 7;
    const float* W = resolve_w(node, slot);
    if (!W) return;
    __shared__ float tile[32][33];
    int n0 = blockIdx.x * 32, k0 = blockIdx.y * 32;
    int tx = threadIdx.x, ty = threadIdx.y;
#pragma unroll
    for (int dy = 0; dy < 4; dy++)
        tile[ty * 4 + dy][tx] = W[(size_t)(k0 + ty * 4 + dy) * DIM + n0 + tx];
    __syncthreads();
    size_t base = (size_t)z * DIM * DIM;
#pragma unroll
    for (int dy = 0; dy < 4; dy++) {
        int n = n0 + ty * 4 + dy, k = k0 + tx;
        g_Wt[base + (size_t)n * DIM + k] = __float2half_rn(tile[tx][ty * 4 + dy]);
    }
}

// ---------------------------------------------------------------------------
// edge_pre: warp-per-row, float4 vectorized. grid (512, 3) block 256
// ---------------------------------------------------------------------------
__global__ void edge_pre(int node) {
    int role = blockIdx.y;
    NR r = g_nr[node];
    int valid, in, op, e; float w; float* out;
    if (role == 0)      { valid = 1;         in = r.q_in; op = r.q_op; e = r.q_e; w = r.q_w; out = g_qv; }
    else if (role == 1) { valid = r.k_valid; in = r.k_in; op = r.k_op; e = r.k_e; w = r.k_w; out = g_kv; }
    else                { valid = r.v_valid; in = r.v_in; op = r.v_op; e = r.v_e; w = r.v_w; out = g_vv; }
    if (!valid) return;
    int warp = threadIdx.x >> 5, lane = threadIdx.x & 31;
    int row = blockIdx.x * 8 + warp;
    size_t rb = (size_t)row * DIM;
    int c0 = lane * 4;
    const float* x = buf_in(in) + rb;
    float4 v4[4];
#pragma unroll
    for (int i = 0; i < 4; i++) v4[i] = *(const float4*)(x + c0 + i * 128);

    __half* exh = g_EXh + (size_t)role * MS + rb;
    __half* exl = g_EXl + (size_t)role * MS + rb;
    if (op <= 2) {
        const float* gm = g_ptrs.edge_g + e * DIM;
        const float* bt = g_ptrs.edge_beta + e * DIM;
        float s = 0.f;
#pragma unroll
        for (int i = 0; i < 4; i++) s += v4[i].x + v4[i].y + v4[i].z + v4[i].w;
        float mean = wsum(s) * (1.0f / 512.0f);
        float q = 0.f;
#pragma unroll
        for (int i = 0; i < 4; i++) {
            float dx = v4[i].x - mean, dy = v4[i].y - mean, dz = v4[i].z - mean, dw = v4[i].w - mean;
            q += dx * dx + dy * dy + dz * dz + dw * dw;
        }
        float inv = rsqrtf(wsum(q) * (1.0f / 512.0f) + EPSLN);
#pragma unroll
        for (int i = 0; i < 4; i++) {
            float4 g4 = *(const float4*)(gm + c0 + i * 128);
            float4 b4 = *(const float4*)(bt + c0 + i * 128);
            float4 y4;
            y4.x = (v4[i].x - mean) * inv * g4.x + b4.x;
            y4.y = (v4[i].y - mean) * inv * g4.y + b4.y;
            y4.z = (v4[i].z - mean) * inv * g4.z + b4.z;
            y4.w = (v4[i].w - mean) * inv * g4.w + b4.w;
            uint2 hi, lo; cvt_hilo(y4, hi, lo);
            *(uint2*)(exh + c0 + i * 128) = hi;
            *(uint2*)(exl + c0 + i * 128) = lo;
        }
    } else if (op == 3) {
#pragma unroll
        for (int i = 0; i < 4; i++) {
            uint2 hi, lo; cvt_hilo(v4[i], hi, lo);
            *(uint2*)(exh + c0 + i * 128) = hi;
            *(uint2*)(exl + c0 + i * 128) = lo;
        }
    } else { // op == 4
        bool nh = need_hilo_role(r.act, role);
        __half* nxh = g_NXh + (size_t)role * MS + rb;
        __half* nxl = g_NXl + (size_t)role * MS + rb;
#pragma unroll
        for (int i = 0; i < 4; i++) {
            float4 y4 = make_float4(w * v4[i].x, w * v4[i].y, w * v4[i].z, w * v4[i].w);
            *(float4*)(out + rb + c0 + i * 128) = y4;
            if (nh) {
                uint2 hi, lo; cvt_hilo(y4, hi, lo);
                *(uint2*)(nxh + c0 + i * 128) = hi;
                *(uint2*)(nxl + c0 + i * 128) = lo;
            }
        }
    }
}

// node prep (act0): NX0 = LN(qv) hi/lo ; warp-per-row, float4 ; grid 512
__global__ void node_prep(int node) {
    NR r = g_nr[node];
    if (r.act != 0) return;
    int warp = threadIdx.x >> 5, lane = threadIdx.x & 31;
    int row = blockIdx.x * 8 + warp;
    size_t rb = (size_t)row * DIM;
    int c0 = lane * 4;
    const float* gm = g_ptrs.node_g + node * DIM;
    const float* bt = g_ptrs.node_beta + node * DIM;
    float4 v4[4];
#pragma unroll
    for (int i = 0; i < 4; i++) v4[i] = *(const float4*)(g_qv + rb + c0 + i * 128);
    float s = 0.f;
#pragma unroll
    for (int i = 0; i < 4; i++) s += v4[i].x + v4[i].y + v4[i].z + v4[i].w;
    float mean = wsum(s) * (1.0f / 512.0f);
    float q = 0.f;
#pragma unroll
    for (int i = 0; i < 4; i++) {
        float dx = v4[i].x - mean, dy = v4[i].y - mean, dz = v4[i].z - mean, dw = v4[i].w - mean;
        q += dx * dx + dy * dy + dz * dz + dw * dw;
    }
    float inv = rsqrtf(wsum(q) * (1.0f / 512.0f) + EPSLN);
#pragma unroll
    for (int i = 0; i < 4; i++) {
        float4 g4 = *(const float4*)(gm + c0 + i * 128);
        float4 b4 = *(const float4*)(bt + c0 + i * 128);
        float4 y4;
        y4.x = (v4[i].x - mean) * inv * g4.x + b4.x;
        y4.y = (v4[i].y - mean) * inv * g4.y + b4.y;
        y4.z = (v4[i].z - mean) * inv * g4.z + b4.z;
        y4.w = (v4[i].w - mean) * inv * g4.w + b4.w;
        uint2 hi, lo; cvt_hilo(y4, hi, lo);
        *(uint2*)(g_NXh + rb + c0 + i * 128) = hi;
        *(uint2*)(g_NXl + rb + c0 + i * 128) = lo;
    }
}

// ---------------------------------------------------------------------------
// GEMM config
// ---------------------------------------------------------------------------
struct GemmCfg {
    const __half *Xh, *Xl, *W;
    const float* Bv;
    int act;            // 0 none, 1 relu, 2 gelu
    float scale;
    const float* res;
    float* out;
    __half *oh, *ol;
};

__device__ bool resolve_gemm(int node, int slot, GemmCfg& g) {
    NR r = g_nr[node];
    g.oh = nullptr; g.ol = nullptr; g.res = nullptr;
    g.W = g_Wt + ((size_t)node * 7 + slot) * DIM * DIM;
    if (slot < 3) {
        int valid, op, e; float w; float* out;
        if (slot == 0)      { valid = 1;         op = r.q_op; e = r.q_e; w = r.q_w; out = g_qv; }
        else if (slot == 1) { valid = r.k_valid; op = r.k_op; e = r.k_e; w = r.k_w; out = g_kv; }
        else                { valid = r.v_valid; op = r.v_op; e = r.v_e; w = r.v_w; out = g_vv; }
        if (!valid || op == 4) return false;
        g.Xh = g_EXh + (size_t)slot * MS;
        g.Xl = g_EXl + (size_t)slot * MS;
        g.Bv = g_ptrs.edge_b + e * DIM;
        g.act = (op == 0) ? 1 : (op == 1) ? 2 : 0;
        g.scale = w; g.out = out;
        if (need_hilo_role(r.act, slot)) {
            g.oh = g_NXh + (size_t)slot * MS;
            g.ol = g_NXl + (size_t)slot * MS;
        }
        return true;
    }
    int a = r.act;
    int j = slot - 3;
    const float* Bv = g_ptrs.node_b + (node * 4 + j) * DIM;
    if (j == 0) {
        if (a != 0 && a != 1 && a != 3) return false;
        g.Xh = g_NXh; g.Xl = g_NXl;
        g.Bv = (a == 3) ? nullptr : Bv;
        g.act = (a == 1) ? 2 : 0;
        g.scale = 1.f; g.out = g_h0;
        return true;
    }
    if (j == 1) {
        if (a != 0 && a != 1 && a != 3 && a != 5) return false;
        g.Xh = g_NXh + (size_t)1 * MS; g.Xl = g_NXl + (size_t)1 * MS;
        g.Bv = (a == 3) ? nullptr : Bv;
        g.act = (a == 5) ? 2 : 0;
        g.scale = 1.f; g.out = g_h1;
        return true;
    }
    if (j == 2) {
        if (a != 0 && a != 3) return false;
        g.Xh = g_NXh + (size_t)2 * MS; g.Xl = g_NXl + (size_t)2 * MS;
        g.Bv = (a == 3) ? nullptr : Bv;
        g.act = 0; g.scale = 1.f; g.out = g_h2;
        return true;
    }
    if (a != 0 && a != 1 && a != 3) return false;
    g.Xh = g_NXh; g.Xl = g_NXl;
    g.Bv = Bv; g.act = 0; g.scale = r.aw;
    g.res = g_qv; g.out = g_outs + (size_t)node * MS;
    return true;
}

// ---------------------------------------------------------------------------
// Pipelined mma GEMM: CTA 128x128, 16 warps (32x32 each), K-chunk 64
// hi product -> f32 acc ; lo product -> f16 acc (negligible error, possibly 2x rate)
// stage: A_h 16K | A_l 16K | B 16K = 48K ; 4-stage ring = 192KB
// block 512 (4 warps/SMSP), grid (4, 32, nz)
// ---------------------------------------------------------------------------
#define GEMM_SMEM 196608
#define STAGE_STRIDE 49152

__global__ void __launch_bounds__(512) gemm_mma(int node, int base_slot) {
    int slot = base_slot + blockIdx.z;
    GemmCfg g;
    if (!resolve_gemm(node, slot, g)) return;

    extern __shared__ char smem[];
    uint32_t sbase = smem_u32(smem);
    int t = threadIdx.x, lane = t & 31, wid = t >> 5;
    int m0 = blockIdx.y * 128, n0 = blockIdx.x * 128;
    int wm = (wid & 3) * 32, wn = (wid >> 2) * 32;

    float acc[2][4][4];
    uint32_t acch[2][4][2];
#pragma unroll
    for (int i = 0; i < 2; i++)
#pragma unroll
        for (int j = 0; j < 4; j++) {
#pragma unroll
            for (int l = 0; l < 4; l++) acc[i][j][l] = 0.f;
            acch[i][j][0] = 0u; acch[i][j][1] = 0u;
        }

    // loaders: 512 threads ; 4 threads/row (128 rows), 16 fp16 (32B) each
    int lrow = t >> 2, lcb = (t & 3) * 16;
    const __half* pAh = g.Xh + (size_t)(m0 + lrow) * DIM + lcb;
    const __half* pAl = g.Xl + (size_t)(m0 + lrow) * DIM + lcb;
    const __half* pB  = g.W  + (size_t)(n0 + lrow) * DIM + lcb;
    uint32_t doff[2];
#pragma unroll
    for (int i = 0; i < 2; i++)
        doff[i] = SW128((uint32_t)(lrow * 128 + (lcb + i * 8) * 2));

    // ldmatrix lane addressing
    int a_r = (lane & 15), a_k8 = (lane >> 4) << 3;
    int b_n = ((lane & 16) >> 1) + (lane & 7), b_k8 = (lane & 8);

    // prologue: stages 0,1 <- chunks 0,1
#pragma unroll
    for (int pc = 0; pc < 2; pc++) {
        uint32_t sb = sbase + pc * STAGE_STRIDE;
        int k0 = pc * 64;
#pragma unroll
        for (int i = 0; i < 2; i++) {
            cpa16(sb + doff[i],         pAh + k0 + i * 8);
            cpa16(sb + 16384 + doff[i], pAl + k0 + i * 8);
            cpa16(sb + 32768 + doff[i], pB  + k0 + i * 8);
        }
        CPA_COMMIT();
    }

    for (int c = 0; c < 8; c++) {
        if (c + 2 < 8) {
            int k0 = (c + 2) * 64;
            uint32_t sb = sbase + ((c + 2) & 3) * STAGE_STRIDE;
#pragma unroll
            for (int i = 0; i < 2; i++) {
                cpa16(sb + doff[i],         pAh + k0 + i * 8);
                cpa16(sb + 16384 + doff[i], pAl + k0 + i * 8);
                cpa16(sb + 32768 + doff[i], pB  + k0 + i * 8);
            }
        }
        CPA_COMMIT();
        CPA_WAIT2();
        __syncthreads();

        uint32_t sA_H = sbase + (c & 3) * STAGE_STRIDE;
        uint32_t sA_L = sA_H + 16384, sB = sA_H + 32768;
#pragma unroll
        for (int kt = 0; kt < 4; kt++) {
            int kb = kt * 16;
            uint32_t ah[2][4], al[2][4];
#pragma unroll
            for (int mt = 0; mt < 2; mt++) {
                uint32_t off = SW128((uint32_t)((wm + mt * 16 + a_r) * 128 + (kb + a_k8) * 2));
                ldm4(sA_H + off, ah[mt]);
                ldm4(sA_L + off, al[mt]);
            }
#pragma unroll
            for (int ng = 0; ng < 2; ng++) {
                uint32_t boff = SW128((uint32_t)((wn + ng * 16 + b_n) * 128 + (kb + b_k8) * 2));
                uint32_t b4[4];
                ldm4(sB + boff, b4);
#pragma unroll
                for (int mt = 0; mt < 2; mt++) {
                    mma16816(acc[mt][2 * ng],     ah[mt], b4[0], b4[1]);
                    mma16816(acc[mt][2 * ng + 1], ah[mt], b4[2], b4[3]);
                    mma16816h(acch[mt][2 * ng],     al[mt], b4[0], b4[1]);
                    mma16816h(acch[mt][2 * ng + 1], al[mt], b4[2], b4[3]);
                }
            }
        }
    }

    // epilogue
#pragma unroll
    for (int mt = 0; mt < 2; mt++) {
        int r0 = m0 + wm + mt * 16 + (lane >> 2);
#pragma unroll
        for (int nt = 0; nt < 4; nt++) {
            int col = n0 + wn + nt * 8 + (lane & 3) * 2;
#pragma unroll
            for (int h = 0; h < 2; h++) {
                int row = r0 + h * 8;
                __half2 lohalf = *(__half2*)&acch[mt][nt][h];
                float v0 = acc[mt][nt][h * 2]     + __half2float(lohalf.x);
                float v1 = acc[mt][nt][h * 2 + 1] + __half2float(lohalf.y);
                if (g.Bv) { v0 += g.Bv[col]; v1 += g.Bv[col + 1]; }
                if (g.act == 1)      { v0 = fmaxf(v0, 0.f); v1 = fmaxf(v1, 0.f); }
                else if (g.act == 2) { v0 = geluf(v0); v1 = geluf(v1); }
                if (g.res) {
                    v0 += g.res[(size_t)row * DIM + col];
                    v1 += g.res[(size_t)row * DIM + col + 1];
                }
                v0 *= g.scale; v1 *= g.scale;
                size_t p = (size_t)row * DIM + col;
                *(float2*)(g.out + p) = make_float2(v0, v1);
                if (g.oh) {
                    __half h0, l0, h1, l1;
                    split_h(v0, h0, l0); split_h(v1, h1, l1);
                    *(uint32_t*)(g.oh + p) =
                        (uint32_t)__half_as_ushort(h0) | ((uint32_t)__half_as_ushort(h1) << 16);
                    *(uint32_t*)(g.ol + p) =
                        (uint32_t)__half_as_ushort(l0) | ((uint32_t)__half_as_ushort(l1) << 16);
                }
            }
        }
    }
}

// ---------------------------------------------------------------------------
// Flash attention (act0): O = softmax(QK^T/8) V  -> NX0 hi/lo
// grid (8, 32), 256 thr (8 warps), warp w owns rows w*16..w*16+15
// smem: Qh 16K | Ql 16K | K 8K | V 8K = 48KB
// ---------------------------------------------------------------------------
__global__ void __launch_bounds__(256) flash_k(int node) {
    if (g_nr[node].act != 0) return;
    extern __shared__ char smem[];
    uint32_t sQ_H = smem_u32(smem);
    uint32_t sQ_L = sQ_H + 16384;
    uint32_t sK = sQ_H + 32768, sV = sQ_H + 40960;

    int t = threadIdx.x, lane = t & 31, wid = t >> 5;
    int bh = blockIdx.y, b = bh >> 3, head = bh & 7;
    int i0 = blockIdx.x * 128;

    const float* Q = g_h0 + (size_t)b * SLEN * DIM + head * DH;
    const float* K = g_h1 + (size_t)b * SLEN * DIM + head * DH;
    const float* V = g_h2 + (size_t)b * SLEN * DIM + head * DH;

    {
        int lrow = t >> 1, lcb = (t & 1) * 32;
        const float* qr = Q + (size_t)(i0 + lrow) * DIM + lcb;
#pragma unroll
        for (int i = 0; i < 8; i++) {
            uint2 hi, lo; cvt_hilo(*(const float4*)(qr + i * 4), hi, lo);
            uint32_t off = SW128((uint32_t)(lrow * 128 + (lcb + i * 4) * 2));
            *(uint2*)(smem + off) = hi;
            *(uint2*)(smem + 16384 + off) = lo;
        }
    }

    float O[8][4];
#pragma unroll
    for (int d = 0; d < 8; d++)
#pragma unroll
        for (int l = 0; l < 4; l++) O[d][l] = 0.f;
    float mrow[2] = {-3.4e38f, -3.4e38f};
    float lrow_[2] = {0.f, 0.f};

    int a_r = (lane & 15), a_k8 = (lane >> 4) << 3;
    int b_n = ((lane & 16) >> 1) + (lane & 7), b_k8 = (lane & 8);
    int v_k = (lane & 15), v_n8 = (lane & 16) >> 1;
    int kvrow = t >> 2, kvcb = (t & 3) * 16;

    for (int jc = 0; jc < 16; jc++) {
        int j0 = jc * 64;
        {
            const float* kr = K + (size_t)(j0 + kvrow) * DIM + kvcb;
            const float* vr = V + (size_t)(j0 + kvrow) * DIM + kvcb;
#pragma unroll
            for (int i = 0; i < 4; i++) {
                uint32_t off = SW128((uint32_t)(kvrow * 128 + (kvcb + i * 4) * 2));
                *(uint2*)(smem + 32768 + off) = cvt_h(*(const float4*)(kr + i * 4));
                *(uint2*)(smem + 40960 + off) = cvt_h(*(const float4*)(vr + i * 4));
            }
        }
        __syncthreads();

        float s[8][4];
#pragma unroll
        for (int j = 0; j < 8; j++)
#pragma unroll
            for (int l = 0; l < 4; l++) s[j][l] = 0.f;
#pragma unroll
        for (int kt = 0; kt < 4; kt++) {
            int kb = kt * 16;
            uint32_t qh[4], ql[4];
            uint32_t qoff = SW128((uint32_t)((wid * 16 + a_r) * 128 + (kb + a_k8) * 2));
            ldm4(sQ_H + qoff, qh);
            ldm4(sQ_L + qoff, ql);
#pragma unroll
            for (int ng = 0; ng < 4; ng++) {
                uint32_t boff = SW128((uint32_t)((ng * 16 + b_n) * 128 + (kb + b_k8) * 2));
                uint32_t k4[4];
                ldm4(sK + boff, k4);
                mma16816(s[2 * ng],     qh, k4[0], k4[1]);
                mma16816(s[2 * ng + 1], qh, k4[2], k4[3]);
                mma16816(s[2 * ng],     ql, k4[0], k4[1]);
                mma16816(s[2 * ng + 1], ql, k4[2], k4[3]);
            }
        }
#pragma unroll
        for (int j = 0; j < 8; j++)
#pragma unroll
            for (int l = 0; l < 4; l++) s[j][l] *= 0.125f;

#pragma unroll
        for (int h = 0; h < 2; h++) {
            float mj = -3.4e38f;
#pragma unroll
            for (int j = 0; j < 8; j++) mj = fmaxf(mj, fmaxf(s[j][h * 2], s[j][h * 2 + 1]));
            mj = fmaxf(mj, __shfl_xor_sync(0xffffffffu, mj, 1));
            mj = fmaxf(mj, __shfl_xor_sync(0xffffffffu, mj, 2));
            float mnew = fmaxf(mrow[h], mj);
            float alpha = expf(mrow[h] - mnew);
            float ps = 0.f;
#pragma unroll
            for (int j = 0; j < 8; j++) {
                s[j][h * 2]     = expf(s[j][h * 2] - mnew);
                s[j][h * 2 + 1] = expf(s[j][h * 2 + 1] - mnew);
                ps += s[j][h * 2] + s[j][h * 2 + 1];
            }
            ps += __shfl_xor_sync(0xffffffffu, ps, 1);
            ps += __shfl_xor_sync(0xffffffffu, ps, 2);
            lrow_[h] = lrow_[h] * alpha + ps;
            mrow[h] = mnew;
#pragma unroll
            for (int d = 0; d < 8; d++) {
                O[d][h * 2]     *= alpha;
                O[d][h * 2 + 1] *= alpha;
            }
        }

#pragma unroll
        for (int g4 = 0; g4 < 4; g4++) {
            uint32_t ah[4], al[4];
            {
                uint2 hi, lo;
                cvt_hilo(make_float4(s[2 * g4][0], s[2 * g4][1], s[2 * g4][2], s[2 * g4][3]), hi, lo);
                ah[0] = hi.x; ah[1] = hi.y; al[0] = lo.x; al[1] = lo.y;
                cvt_hilo(make_float4(s[2 * g4 + 1][0], s[2 * g4 + 1][1], s[2 * g4 + 1][2], s[2 * g4 + 1][3]), hi, lo);
                ah[2] = hi.x; ah[3] = hi.y; al[2] = lo.x; al[3] = lo.y;
            }
            int kb = g4 * 16;
#pragma unroll
            for (int ng = 0; ng < 4; ng++) {
                uint32_t boff = SW128((uint32_t)((kb + v_k) * 128 + (ng * 16 + v_n8) * 2));
                uint32_t v4[4];
                ldm4t(sV + boff, v4);
                mma16816(O[2 * ng],     ah, v4[0], v4[1]);
                mma16816(O[2 * ng + 1], ah, v4[2], v4[3]);
                mma16816(O[2 * ng],     al, v4[0], v4[1]);
                mma16816(O[2 * ng + 1], al, v4[2], v4[3]);
            }
        }
        __syncthreads();
    }

    float inv0 = 1.0f / lrow_[0], inv1 = 1.0f / lrow_[1];
    __half* Oh = g_NXh + ((size_t)b * SLEN) * DIM + head * DH;
    __half* Ol = g_NXl + ((size_t)b * SLEN) * DIM + head * DH;
    int r0 = i0 + wid * 16 + (lane >> 2);
#pragma unroll
    for (int d = 0; d < 8; d++) {
        int col = d * 8 + (lane & 3) * 2;
#pragma unroll
        for (int h = 0; h < 2; h++) {
            int row = r0 + h * 8;
            float inv = h ? inv1 : inv0;
            float v0 = O[d][h * 2] * inv, v1 = O[d][h * 2 + 1] * inv;
            __half h0, l0, h1, l1;
            split_h(v0, h0, l0); split_h(v1, h1, l1);
            size_t p = (size_t)row * DIM + col;
            *(uint32_t*)(Oh + p) =
                (uint32_t)__half_as_ushort(h0) | ((uint32_t)__half_as_ushort(h1) << 16);
            *(uint32_t*)(Ol + p) =
                (uint32_t)__half_as_ushort(l0) | ((uint32_t)__half_as_ushort(l1) << 16);
        }
    }
}

// ---------------------------------------------------------------------------
// post_k: fused combine (acts 1,3 -> NX0 hi/lo) + finish (acts 2,4,5,6,7).
// Valid before the slot-6 GEMM: finish acts and slot-6 acts are disjoint.
// warp-per-row, float4 ; grid 512
// ---------------------------------------------------------------------------
__global__ void post_k(int node) {
    NR r = g_nr[node];
    int a = r.act;
    if (a == 0) return;
    int warp = threadIdx.x >> 5, lane = threadIdx.x & 31;
    int row = blockIdx.x * 8 + warp;
    size_t rb = (size_t)row * DIM;
    int c0 = lane * 4;

    if (a == 1 || a == 3) {
        // combine -> NX0 hi/lo
#pragma unroll
        for (int i = 0; i < 4; i++) {
            size_t p = rb + c0 + i * 128;
            float4 a4 = *(const float4*)(g_h0 + p);
            float4 b4 = *(const float4*)(g_h1 + p);
            float4 y4;
            if (a == 1) {
                y4 = make_float4(a4.x * b4.x, a4.y * b4.y, a4.z * b4.z, a4.w * b4.w);
            } else {
                float4 cc4 = *(const float4*)(g_h2 + p);
                y4 = make_float4(fmaxf(a4.x + b4.x + cc4.x, 0.f), fmaxf(a4.y + b4.y + cc4.y, 0.f),
                                 fmaxf(a4.z + b4.z + cc4.z, 0.f), fmaxf(a4.w + b4.w + cc4.w, 0.f));
            }
            uint2 hi, lo; cvt_hilo(y4, hi, lo);
            *(uint2*)(g_NXh + p) = hi;
            *(uint2*)(g_NXl + p) = lo;
        }
        return;
    }

    float* out = g_outs + (size_t)node * MS + rb;
    if (a == 4 || a == 5 || a == 6) {
#pragma unroll
        for (int i = 0; i < 4; i++) {
            size_t p = rb + c0 + i * 128;
            float4 q4 = *(const float4*)(g_qv + p);
            float4 y4;
            if (a == 4) {
                float4 k4 = *(const float4*)(g_kv + p);
                float4 v4 = *(const float4*)(g_vv + p);
                y4 = make_float4(q4.x * sigmoidf_(k4.x) + v4.x, q4.y * sigmoidf_(k4.y) + v4.y,
                                 q4.z * sigmoidf_(k4.z) + v4.z, q4.w * sigmoidf_(k4.w) + v4.w);
            } else if (a == 5) {
                float4 h4 = *(const float4*)(g_h1 + p);
                y4 = make_float4(q4.x + h4.x, q4.y + h4.y, q4.z + h4.z, q4.w + h4.w);
            } else {
                float4 k4 = *(const float4*)(g_kv + p);
                y4 = make_float4(q4.x + k4.x, q4.y + k4.y, q4.z + k4.z, q4.w + k4.w);
            }
            *(float4*)(out + c0 + i * 128) =
                make_float4(r.aw * y4.x, r.aw * y4.y, r.aw * y4.z, r.aw * y4.w);
        }
        return;
    }
    // a == 2 or 7: LN
    float4 v4[4];
#pragma unroll
    for (int i = 0; i < 4; i++) {
        size_t p = rb + c0 + i * 128;
        float4 q4 = *(const float4*)(g_qv + p);
        if (a == 2) {
            float4 k4 = *(const float4*)(g_kv + p);
            float4 w4 = *(const float4*)(g_vv + p);
            v4[i] = make_float4(q4.x + k4.x + w4.x, q4.y + k4.y + w4.y,
                                q4.z + k4.z + w4.z, q4.w + k4.w + w4.w);
        } else {
            v4[i] = q4;
        }
    }
    float s = 0.f;
#pragma unroll
    for (int i = 0; i < 4; i++) s += v4[i].x + v4[i].y + v4[i].z + v4[i].w;
    float mean = wsum(s) * (1.0f / 512.0f);
    float q = 0.f;
#pragma unroll
    for (int i = 0; i < 4; i++) {
        float dx = v4[i].x - mean, dy = v4[i].y - mean, dz = v4[i].z - mean, dw = v4[i].w - mean;
        q += dx * dx + dy * dy + dz * dz + dw * dw;
    }
    float inv = rsqrtf(wsum(q) * (1.0f / 512.0f) + EPSLN);
    const float* gm = g_ptrs.node_g + node * DIM;
    const float* bt = g_ptrs.node_beta + node * DIM;
#pragma unroll
    for (int i = 0; i < 4; i++) {
        float4 g4 = *(const float4*)(gm + c0 + i * 128);
        float4 b4 = *(const float4*)(bt + c0 + i * 128);
        *(float4*)(out + c0 + i * 128) = make_float4(
            r.aw * ((v4[i].x - mean) * inv * g4.x + b4.x),
            r.aw * ((v4[i].y - mean) * inv * g4.y + b4.y),
            r.aw * ((v4[i].z - mean) * inv * g4.z + b4.z),
            r.aw * ((v4[i].w - mean) * inv * g4.w + b4.w));
    }
}

// final: sum unprocessed + LN ; warp-per-row, float4 ; grid 512
__global__ void final_k(float* dout) {
    int warp = threadIdx.x >> 5, lane = threadIdx.x & 31;
    int row = blockIdx.x * 8 + warp;
    size_t rb = (size_t)row * DIM;
    int c0 = lane * 4;
    float4 v4[4];
#pragma unroll
    for (int i = 0; i < 4; i++) v4[i] = make_float4(0.f, 0.f, 0.f, 0.f);
    for (int c = 0; c < 8; c++) {
        if (!g_processed[c]) {
            const float* o = g_outs + (size_t)c * MS + rb;
#pragma unroll
            for (int i = 0; i < 4; i++) {
                float4 t4 = *(const float4*)(o + c0 + i * 128);
                v4[i].x += t4.x; v4[i].y += t4.y; v4[i].z += t4.z; v4[i].w += t4.w;
            }
        }
    }
    float s = 0.f;
#pragma unroll
    for (int i = 0; i < 4; i++) s += v4[i].x + v4[i].y + v4[i].z + v4[i].w;
    float mean = wsum(s) * (1.0f / 512.0f);
    float q = 0.f;
#pragma unroll
    for (int i = 0; i < 4; i++) {
        float dx = v4[i].x - mean, dy = v4[i].y - mean, dz = v4[i].z - mean, dw = v4[i].w - mean;
        q += dx * dx + dy * dy + dz * dz + dw * dw;
    }
    float inv = rsqrtf(wsum(q) * (1.0f / 512.0f) + EPSLN);
#pragma unroll
    for (int i = 0; i < 4; i++) {
        float4 g4 = *(const float4*)(g_ptrs.out_g + c0 + i * 128);
        float4 b4 = *(const float4*)(g_ptrs.out_beta + c0 + i * 128);
        *(float4*)(dout + rb + c0 + i * 128) = make_float4(
            (v4[i].x - mean) * inv * g4.x + b4.x,
            (v4[i].y - mean) * inv * g4.y + b4.y,
            (v4[i].z - mean) * inv * g4.z + b4.z,
            (v4[i].w - mean) * inv * g4.w + b4.w);
    }
}

// ---------------------------------------------------------------------------
// Launch
// ---------------------------------------------------------------------------
extern "C" void kernel_launch(void* const* d_in, const int* in_sizes, int n_in,
                              void* d_out, int out_size) {
    (void)in_sizes; (void)n_in; (void)out_size;
    cudaFuncSetAttribute(gemm_mma, cudaFuncAttributeMaxDynamicSharedMemorySize, GEMM_SMEM);
    cudaFuncSetAttribute(flash_k,  cudaFuncAttributeMaxDynamicSharedMemorySize, 49152);

    setup_k<<<1, 1>>>(
        (const float*)d_in[0],  (const float*)d_in[1],  (const float*)d_in[2],
        (const float*)d_in[3],  (const float*)d_in[4],  (const float*)d_in[5],
        (const float*)d_in[6],  (const float*)d_in[7],  (const float*)d_in[8],
        (const float*)d_in[9],  (const float*)d_in[10], (const float*)d_in[11],
        (const float*)d_in[12], (const float*)d_in[13]);
    routing_k<<<1, 1>>>();
    conv_w_all<<<dim3(16, 16, 56), dim3(32, 8)>>>();

    for (int c = 0; c < 8; c++) {
        edge_pre<<<dim3(512, 3), 256>>>(c);
        gemm_mma<<<dim3(4, 32, 3), 512, GEMM_SMEM>>>(c, 0);   // edge q/k/v
        node_prep<<<512, 256>>>(c);
        gemm_mma<<<dim3(4, 32, 3), 512, GEMM_SMEM>>>(c, 3);   // node j0/j1/j2
        flash_k<<<dim3(8, 32), 256, 49152>>>(c);
        post_k<<<512, 256>>>(c);                              // combine + finish
        gemm_mma<<<dim3(4, 32, 1), 512, GEMM_SMEM>>>(c, 6);   // node j3
    }
    final_k<<<512, 256>>>((float*)d_out);
}

// round 14
// speedup vs baseline: 1.0377x; 1.0377x over previous
#include <cuda_runtime.h>
#include <cuda_fp16.h>
#include <math.h>
#include <stdint.h>

// ---------------------------------------------------------------------------
// Problem constants
// ---------------------------------------------------------------------------
#define NROWS 4096          // B*SLEN
#define DIM   512
#define MS    (4096*512)
#define NHEAD 8
#define DH    64
#define SLEN  1024
#define EPSLN 1e-6f

// ---------------------------------------------------------------------------
// Device-resident input pointer table + route table
// ---------------------------------------------------------------------------
struct Ptrs {
    const float *inpute, *inputo, *node_p, *edge_p;
    const float *edge_W, *edge_b, *edge_g, *edge_beta;
    const float *node_W, *node_b, *node_g, *node_beta;
    const float *out_g, *out_beta;
};
__device__ Ptrs g_ptrs;

struct NR {
    int act; float aw;
    int q_in, q_op, q_e; float q_w;
    int k_valid, k_in, k_op, k_e; float k_w;
    int v_valid, v_in, v_op, v_e; float v_w;
};
__device__ NR  g_nr[8];
__device__ int g_processed[8];

// ---------------------------------------------------------------------------
// Scratch
// ---------------------------------------------------------------------------
__device__ float g_outs[8 * MS];
__device__ float g_qv[MS], g_kv[MS], g_vv[MS];
__device__ float g_h0[MS], g_h1[MS], g_h2[MS];
__device__ __align__(16) __half g_EXh[3 * MS], g_EXl[3 * MS];   // edge GEMM A inputs (hi/lo fp16)
__device__ __align__(16) __half g_NXh[3 * MS], g_NXl[3 * MS];   // node GEMM A inputs
__device__ __align__(16) __half g_Wt[8 * 7 * DIM * DIM];        // W^T single fp16 [node][slot][n][k]

// ---------------------------------------------------------------------------
// Helpers
// ---------------------------------------------------------------------------
__device__ __forceinline__ const float* buf_in(int idx) {
    if (idx == 0) return g_ptrs.inpute;
    if (idx == 1) return g_ptrs.inputo;
    return g_outs + (size_t)(idx - 2) * MS;
}

__device__ __forceinline__ float geluf(float x) {
    float x3 = x * x * x;
    return 0.5f * x * (1.0f + tanhf(0.7978845608028654f * (x + 0.044715f * x3)));
}
__device__ __forceinline__ float sigmoidf_(float x) {
    return 1.0f / (1.0f + expf(-x));
}

__device__ __forceinline__ float wsum(float v) {
#pragma unroll
    for (int o = 16; o; o >>= 1) v += __shfl_xor_sync(0xffffffffu, v, o);
    return v;
}

__device__ __forceinline__ void split_h(float v, __half& h, __half& l) {
    h = __float2half_rn(v);
    l = __float2half_rn(v - __half2float(h));
}

// ---------------------------------------------------------------------------
// mma.sync / ldmatrix / cp.async helpers
// ---------------------------------------------------------------------------
__device__ __forceinline__ uint32_t smem_u32(const void* p) {
    uint32_t a;
    asm("{ .reg .u64 t; cvta.to.shared.u64 t, %1; cvt.u32.u64 %0, t; }" : "=r"(a) : "l"(p));
    return a;
}
__device__ __forceinline__ void ldm4(uint32_t addr, uint32_t r[4]) {
    asm volatile("ldmatrix.sync.aligned.m8n8.x4.shared.b16 {%0,%1,%2,%3}, [%4];"
                 : "=r"(r[0]), "=r"(r[1]), "=r"(r[2]), "=r"(r[3]) : "r"(addr));
}
__device__ __forceinline__ void ldm4t(uint32_t addr, uint32_t r[4]) {
    asm volatile("ldmatrix.sync.aligned.m8n8.x4.trans.shared.b16 {%0,%1,%2,%3}, [%4];"
                 : "=r"(r[0]), "=r"(r[1]), "=r"(r[2]), "=r"(r[3]) : "r"(addr));
}
__device__ __forceinline__ void mma16816(float c[4], const uint32_t a[4],
                                         uint32_t b0, uint32_t b1) {
    asm volatile(
        "mma.sync.aligned.m16n8k16.row.col.f32.f16.f16.f32 "
        "{%0,%1,%2,%3}, {%4,%5,%6,%7}, {%8,%9}, {%0,%1,%2,%3};"
        : "+f"(c[0]), "+f"(c[1]), "+f"(c[2]), "+f"(c[3])
        : "r"(a[0]), "r"(a[1]), "r"(a[2]), "r"(a[3]), "r"(b0), "r"(b1));
}
__device__ __forceinline__ void cpa16(uint32_t dst, const void* src) {
    asm volatile("cp.async.ca.shared.global [%0], [%1], 16;" :: "r"(dst), "l"(src));
}
#define CPA_COMMIT() asm volatile("cp.async.commit_group;" ::: "memory")
#define CPA_WAIT2()  asm volatile("cp.async.wait_group 2;" ::: "memory")

#define SW128(o) ((o) ^ (((o) >> 3) & 0x70))

__device__ __forceinline__ uint32_t pack_h2(float x, float y) {
    __half2 h = __float22half2_rn(make_float2(x, y));
    return *(uint32_t*)&h;
}
__device__ __forceinline__ void cvt_hilo(float4 v, uint2& hi, uint2& lo) {
    hi = make_uint2(pack_h2(v.x, v.y), pack_h2(v.z, v.w));
    __half2 h0 = *(__half2*)&hi.x;
    __half2 h1 = *(__half2*)&hi.y;
    float lx = v.x - __half2float(h0.x);
    float ly = v.y - __half2float(h0.y);
    float lz = v.z - __half2float(h1.x);
    float lw = v.w - __half2float(h1.y);
    lo = make_uint2(pack_h2(lx, ly), pack_h2(lz, lw));
}
__device__ __forceinline__ uint2 cvt_h(float4 v) {
    return make_uint2(pack_h2(v.x, v.y), pack_h2(v.z, v.w));
}

// ---------------------------------------------------------------------------
// Setup + routing
// ---------------------------------------------------------------------------
__global__ void setup_k(const float* a0, const float* a1, const float* a2, const float* a3,
                        const float* a4, const float* a5, const float* a6, const float* a7,
                        const float* a8, const float* a9, const float* a10, const float* a11,
                        const float* a12, const float* a13) {
    Ptrs p;
    p.inpute = a0; p.inputo = a1; p.node_p = a2; p.edge_p = a3;
    p.edge_W = a4; p.edge_b = a5; p.edge_g = a6; p.edge_beta = a7;
    p.node_W = a8; p.node_b = a9; p.node_g = a10; p.node_beta = a11;
    p.out_g = a12; p.out_beta = a13;
    g_ptrs = p;
}

__device__ int d_amax(const float* x, int n, int lo) {
    int bi = lo; float bv = x[lo];
    for (int i = lo + 1; i < n; i++) { if (x[i] > bv) { bv = x[i]; bi = i; } }
    return bi;
}
__device__ float d_smw(const float* x, int n, int lo, int sel) {
    float mx = x[lo];
    for (int i = lo + 1; i < n; i++) mx = fmaxf(mx, x[i]);
    float s = 0.f;
    for (int i = lo; i < n; i++) s += expf(x[i] - mx);
    return expf(x[sel] - mx) / s;
}

__global__ void routing_k() {
    if (threadIdx.x || blockIdx.x) return;
    const float* np = g_ptrs.node_p;
    const float* ep = g_ptrs.edge_p;
    for (int i = 0; i < 8; i++) g_processed[i] = 0;
    int lind = 0;
    for (int c = 0; c < 8; c++) {
        int nsrc = (c + 2 < 5) ? c + 2 : 5;
        int snode = c - nsrc;
        int n = nsrc * 5;
        const float* e0 = ep + 0 * 170 + lind * 5;
        const float* e1 = ep + 1 * 170 + lind * 5;
        const float* e2 = ep + 2 * 170 + lind * 5;
        NR r; r.k_valid = 0; r.v_valid = 0;
        r.k_in = 0; r.k_op = 4; r.k_e = 0; r.k_w = 0.f;
        r.v_in = 0; r.v_op = 4; r.v_e = 0; r.v_w = 0.f;

        int nact = d_amax(np + c * 8, 8, 0);
        r.act = nact;
        r.aw = d_smw(np + c * 8, 8, 0, nact);

        int qs = d_amax(e0, n, 5);
        int qse = qs / 5;
        r.q_in = (qse == 0) ? 0 : (snode + qse + 2);
        r.q_op = qs % 5; r.q_e = lind + qse;
        r.q_w = d_smw(e0, n, 5, qs);
        if (r.q_in >= 2) g_processed[r.q_in - 2] = 1;

        if (nact < 7) {
            int lo = (nact > 0) ? 5 : 0;
            int ks = d_amax(e1, n, lo);
            int kse = ks / 5;
            r.k_valid = 1;
            r.k_in = (kse == 0) ? 0 : (snode + kse + 2);
            r.k_op = ks % 5; r.k_e = lind + kse;
            r.k_w = d_smw(e1, n, lo, ks);
            if (r.k_in >= 2) g_processed[r.k_in - 2] = 1;
            int ktype = (kse == 0) ? -2 : -1;
            if (nact < 5) {
                r.v_valid = 1;
                int vs, vlo, vn;
                if (nact == 0 && ktype == -2) { vlo = 0; vn = 5; }
                else if (nact > 0)            { vlo = 5; vn = n; }
                else                          { vlo = 0; vn = n; }
                vs = d_amax(e2, vn, vlo);
                int vse = vs / 5;
                r.v_in = (vse == 0) ? 0 : (snode + vse + 2);
                r.v_op = vs % 5; r.v_e = lind + vse;
                r.v_w = d_smw(e2, vn, vlo, vs);
                if (r.v_in >= 2) g_processed[r.v_in - 2] = 1;
            }
        }
        g_nr[c] = r;
        lind += nsrc;
    }
}

// role r output feeds node GEMM slot 3+r?
__device__ __forceinline__ bool need_hilo_role(int act, int role) {
    if (role == 0) return act == 1 || act == 3;
    if (role == 1) return act == 0 || act == 1 || act == 3 || act == 5;
    return act == 0 || act == 3;
}

// ---------------------------------------------------------------------------
// Weight selection for slot 0..6
// ---------------------------------------------------------------------------
__device__ const float* resolve_w(int node, int slot) {
    NR r = g_nr[node];
    if (slot < 3) {
        int valid, op, e;
        if (slot == 0)      { valid = 1;         op = r.q_op; e = r.q_e; }
        else if (slot == 1) { valid = r.k_valid; op = r.k_op; e = r.k_e; }
        else                { valid = r.v_valid; op = r.v_op; e = r.v_e; }
        if (valid && op <= 3) return g_ptrs.edge_W + (size_t)e * DIM * DIM;
        return nullptr;
    }
    int a = r.act, j = slot - 3;
    bool need =
        (j == 0 && (a == 0 || a == 1 || a == 3)) ||
        (j == 1 && (a == 0 || a == 1 || a == 3 || a == 5)) ||
        (j == 2 && (a == 0 || a == 3)) ||
        (j == 3 && (a == 0 || a == 1 || a == 3));
    if (need) return g_ptrs.node_W + ((size_t)node * 4 + j) * DIM * DIM;
    return nullptr;
}

// Convert+transpose W -> single fp16.  grid (16,16,56) block (32,8)
__global__ void conv_w_all() {
    int z = blockIdx.z; int node = z / 7, slot = z % 7;
    const float* W = resolve_w(node, slot);
    if (!W) return;
    __shared__ float tile[32][33];
    int n0 = blockIdx.x * 32, k0 = blockIdx.y * 32;
    int tx = threadIdx.x, ty = threadIdx.y;
#pragma unroll
    for (int dy = 0; dy < 4; dy++)
        tile[ty * 4 + dy][tx] = W[(size_t)(k0 + ty * 4 + dy) * DIM + n0 + tx];
    __syncthreads();
    size_t base = (size_t)z * DIM * DIM;
#pragma unroll
    for (int dy = 0; dy < 4; dy++) {
        int n = n0 + ty * 4 + dy, k = k0 + tx;
        g_Wt[base + (size_t)n * DIM + k] = __float2half_rn(tile[tx][ty * 4 + dy]);
    }
}

// ---------------------------------------------------------------------------
// edge_pre: 2 rows per warp (MLP boost), float4 vectorized.
// grid (256, 3) block 256 (8 warps -> 16 rows/block)
// ---------------------------------------------------------------------------
__global__ void edge_pre(int node) {
    int role = blockIdx.y;
    NR r = g_nr[node];
    int valid, in, op, e; float w; float* out;
    if (role == 0)      { valid = 1;         in = r.q_in; op = r.q_op; e = r.q_e; w = r.q_w; out = g_qv; }
    else if (role == 1) { valid = r.k_valid; in = r.k_in; op = r.k_op; e = r.k_e; w = r.k_w; out = g_kv; }
    else                { valid = r.v_valid; in = r.v_in; op = r.v_op; e = r.v_e; w = r.v_w; out = g_vv; }
    if (!valid) return;
    int warp = threadIdx.x >> 5, lane = threadIdx.x & 31;
    int row0 = (blockIdx.x * 8 + warp) * 2;     // rows row0, row0+1
    int c0 = lane * 4;
    const float* x = buf_in(in);
    size_t rbA = (size_t)row0 * DIM, rbB = rbA + DIM;

    // issue all 8 loads up-front (MLP 8)
    float4 vA[4], vB[4];
#pragma unroll
    for (int i = 0; i < 4; i++) vA[i] = *(const float4*)(x + rbA + c0 + i * 128);
#pragma unroll
    for (int i = 0; i < 4; i++) vB[i] = *(const float4*)(x + rbB + c0 + i * 128);

    __half* exh = g_EXh + (size_t)role * MS;
    __half* exl = g_EXl + (size_t)role * MS;

    if (op <= 2) {
        const float* gm = g_ptrs.edge_g + e * DIM;
        const float* bt = g_ptrs.edge_beta + e * DIM;
        float4 g4[4], b4[4];
#pragma unroll
        for (int i = 0; i < 4; i++) {
            g4[i] = *(const float4*)(gm + c0 + i * 128);
            b4[i] = *(const float4*)(bt + c0 + i * 128);
        }
#pragma unroll
        for (int rr = 0; rr < 2; rr++) {
            float4* v4 = rr ? vB : vA;
            size_t rb = rr ? rbB : rbA;
            float s = 0.f;
#pragma unroll
            for (int i = 0; i < 4; i++) s += v4[i].x + v4[i].y + v4[i].z + v4[i].w;
            float mean = wsum(s) * (1.0f / 512.0f);
            float q = 0.f;
#pragma unroll
            for (int i = 0; i < 4; i++) {
                float dx = v4[i].x - mean, dy = v4[i].y - mean, dz = v4[i].z - mean, dw = v4[i].w - mean;
                q += dx * dx + dy * dy + dz * dz + dw * dw;
            }
            float inv = rsqrtf(wsum(q) * (1.0f / 512.0f) + EPSLN);
#pragma unroll
            for (int i = 0; i < 4; i++) {
                float4 y4;
                y4.x = (v4[i].x - mean) * inv * g4[i].x + b4[i].x;
                y4.y = (v4[i].y - mean) * inv * g4[i].y + b4[i].y;
                y4.z = (v4[i].z - mean) * inv * g4[i].z + b4[i].z;
                y4.w = (v4[i].w - mean) * inv * g4[i].w + b4[i].w;
                uint2 hi, lo; cvt_hilo(y4, hi, lo);
                *(uint2*)(exh + rb + c0 + i * 128) = hi;
                *(uint2*)(exl + rb + c0 + i * 128) = lo;
            }
        }
    } else if (op == 3) {
#pragma unroll
        for (int rr = 0; rr < 2; rr++) {
            float4* v4 = rr ? vB : vA;
            size_t rb = rr ? rbB : rbA;
#pragma unroll
            for (int i = 0; i < 4; i++) {
                uint2 hi, lo; cvt_hilo(v4[i], hi, lo);
                *(uint2*)(exh + rb + c0 + i * 128) = hi;
                *(uint2*)(exl + rb + c0 + i * 128) = lo;
            }
        }
    } else { // op == 4
        bool nh = need_hilo_role(r.act, role);
        __half* nxh = g_NXh + (size_t)role * MS;
        __half* nxl = g_NXl + (size_t)role * MS;
#pragma unroll
        for (int rr = 0; rr < 2; rr++) {
            float4* v4 = rr ? vB : vA;
            size_t rb = rr ? rbB : rbA;
#pragma unroll
            for (int i = 0; i < 4; i++) {
                float4 y4 = make_float4(w * v4[i].x, w * v4[i].y, w * v4[i].z, w * v4[i].w);
                *(float4*)(out + rb + c0 + i * 128) = y4;
                if (nh) {
                    uint2 hi, lo; cvt_hilo(y4, hi, lo);
                    *(uint2*)(nxh + rb + c0 + i * 128) = hi;
                    *(uint2*)(nxl + rb + c0 + i * 128) = lo;
                }
            }
        }
    }
}

// node prep (act0): NX0 = LN(qv) hi/lo ; warp-per-row, float4 ; grid 512
__global__ void node_prep(int node) {
    NR r = g_nr[node];
    if (r.act != 0) return;
    int warp = threadIdx.x >> 5, lane = threadIdx.x & 31;
    int row = blockIdx.x * 8 + warp;
    size_t rb = (size_t)row * DIM;
    int c0 = lane * 4;
    const float* gm = g_ptrs.node_g + node * DIM;
    const float* bt = g_ptrs.node_beta + node * DIM;
    float4 v4[4];
#pragma unroll
    for (int i = 0; i < 4; i++) v4[i] = *(const float4*)(g_qv + rb + c0 + i * 128);
    float s = 0.f;
#pragma unroll
    for (int i = 0; i < 4; i++) s += v4[i].x + v4[i].y + v4[i].z + v4[i].w;
    float mean = wsum(s) * (1.0f / 512.0f);
    float q = 0.f;
#pragma unroll
    for (int i = 0; i < 4; i++) {
        float dx = v4[i].x - mean, dy = v4[i].y - mean, dz = v4[i].z - mean, dw = v4[i].w - mean;
        q += dx * dx + dy * dy + dz * dz + dw * dw;
    }
    float inv = rsqrtf(wsum(q) * (1.0f / 512.0f) + EPSLN);
#pragma unroll
    for (int i = 0; i < 4; i++) {
        float4 g4 = *(const float4*)(gm + c0 + i * 128);
        float4 b4 = *(const float4*)(bt + c0 + i * 128);
        float4 y4;
        y4.x = (v4[i].x - mean) * inv * g4.x + b4.x;
        y4.y = (v4[i].y - mean) * inv * g4.y + b4.y;
        y4.z = (v4[i].z - mean) * inv * g4.z + b4.z;
        y4.w = (v4[i].w - mean) * inv * g4.w + b4.w;
        uint2 hi, lo; cvt_hilo(y4, hi, lo);
        *(uint2*)(g_NXh + rb + c0 + i * 128) = hi;
        *(uint2*)(g_NXl + rb + c0 + i * 128) = lo;
    }
}

// ---------------------------------------------------------------------------
// GEMM config
// ---------------------------------------------------------------------------
struct GemmCfg {
    const __half *Xh, *Xl, *W;
    const float* Bv;
    int act;            // 0 none, 1 relu, 2 gelu
    float scale;
    const float* res;
    float* out;
    __half *oh, *ol;
};

__device__ bool resolve_gemm(int node, int slot, GemmCfg& g) {
    NR r = g_nr[node];
    g.oh = nullptr; g.ol = nullptr; g.res = nullptr;
    g.W = g_Wt + ((size_t)node * 7 + slot) * DIM * DIM;
    if (slot < 3) {
        int valid, op, e; float w; float* out;
        if (slot == 0)      { valid = 1;         op = r.q_op; e = r.q_e; w = r.q_w; out = g_qv; }
        else if (slot == 1) { valid = r.k_valid; op = r.k_op; e = r.k_e; w = r.k_w; out = g_kv; }
        else                { valid = r.v_valid; op = r.v_op; e = r.v_e; w = r.v_w; out = g_vv; }
        if (!valid || op == 4) return false;
        g.Xh = g_EXh + (size_t)slot * MS;
        g.Xl = g_EXl + (size_t)slot * MS;
        g.Bv = g_ptrs.edge_b + e * DIM;
        g.act = (op == 0) ? 1 : (op == 1) ? 2 : 0;
        g.scale = w; g.out = out;
        if (need_hilo_role(r.act, slot)) {
            g.oh = g_NXh + (size_t)slot * MS;
            g.ol = g_NXl + (size_t)slot * MS;
        }
        return true;
    }
    int a = r.act;
    int j = slot - 3;
    const float* Bv = g_ptrs.node_b + (node * 4 + j) * DIM;
    if (j == 0) {
        if (a != 0 && a != 1 && a != 3) return false;
        g.Xh = g_NXh; g.Xl = g_NXl;
        g.Bv = (a == 3) ? nullptr : Bv;
        g.act = (a == 1) ? 2 : 0;
        g.scale = 1.f; g.out = g_h0;
        return true;
    }
    if (j == 1) {
        if (a != 0 && a != 1 && a != 3 && a != 5) return false;
        g.Xh = g_NXh + (size_t)1 * MS; g.Xl = g_NXl + (size_t)1 * MS;
        g.Bv = (a == 3) ? nullptr : Bv;
        g.act = (a == 5) ? 2 : 0;
        g.scale = 1.f; g.out = g_h1;
        return true;
    }
    if (j == 2) {
        if (a != 0 && a != 3) return false;
        g.Xh = g_NXh + (size_t)2 * MS; g.Xl = g_NXl + (size_t)2 * MS;
        g.Bv = (a == 3) ? nullptr : Bv;
        g.act = 0; g.scale = 1.f; g.out = g_h2;
        return true;
    }
    if (a != 0 && a != 1 && a != 3) return false;
    g.Xh = g_NXh; g.Xl = g_NXl;
    g.Bv = Bv; g.act = 0; g.scale = r.aw;
    g.res = g_qv; g.out = g_outs + (size_t)node * MS;
    return true;
}

// ---------------------------------------------------------------------------
// Pipelined mma GEMM (2-product fp16, fp32 acc): CTA 128x128, 16 warps (32x32),
// K-chunk 64 ; stage: A_h 16K | A_l 16K | B 16K = 48K ; 4-stage ring = 192KB
// block 512 (4 warps/SMSP), grid (4, 32, nz)
// ---------------------------------------------------------------------------
#define GEMM_SMEM 196608
#define STAGE_STRIDE 49152

__global__ void __launch_bounds__(512) gemm_mma(int node, int base_slot) {
    int slot = base_slot + blockIdx.z;
    GemmCfg g;
    if (!resolve_gemm(node, slot, g)) return;

    extern __shared__ char smem[];
    uint32_t sbase = smem_u32(smem);
    int t = threadIdx.x, lane = t & 31, wid = t >> 5;
    int m0 = blockIdx.y * 128, n0 = blockIdx.x * 128;
    int wm = (wid & 3) * 32, wn = (wid >> 2) * 32;

    float acc[2][4][4];
#pragma unroll
    for (int i = 0; i < 2; i++)
#pragma unroll
        for (int j = 0; j < 4; j++)
#pragma unroll
            for (int l = 0; l < 4; l++) acc[i][j][l] = 0.f;

    // loaders: 512 threads ; 4 threads/row (128 rows), 16 fp16 (32B) each
    int lrow = t >> 2, lcb = (t & 3) * 16;
    const __half* pAh = g.Xh + (size_t)(m0 + lrow) * DIM + lcb;
    const __half* pAl = g.Xl + (size_t)(m0 + lrow) * DIM + lcb;
    const __half* pB  = g.W  + (size_t)(n0 + lrow) * DIM + lcb;
    uint32_t doff[2];
#pragma unroll
    for (int i = 0; i < 2; i++)
        doff[i] = SW128((uint32_t)(lrow * 128 + (lcb + i * 8) * 2));

    // ldmatrix lane addressing
    int a_r = (lane & 15), a_k8 = (lane >> 4) << 3;
    int b_n = ((lane & 16) >> 1) + (lane & 7), b_k8 = (lane & 8);

    // prologue: stages 0,1 <- chunks 0,1
#pragma unroll
    for (int pc = 0; pc < 2; pc++) {
        uint32_t sb = sbase + pc * STAGE_STRIDE;
        int k0 = pc * 64;
#pragma unroll
        for (int i = 0; i < 2; i++) {
            cpa16(sb + doff[i],         pAh + k0 + i * 8);
            cpa16(sb + 16384 + doff[i], pAl + k0 + i * 8);
            cpa16(sb + 32768 + doff[i], pB  + k0 + i * 8);
        }
        CPA_COMMIT();
    }

    for (int c = 0; c < 8; c++) {
        if (c + 2 < 8) {
            int k0 = (c + 2) * 64;
            uint32_t sb = sbase + ((c + 2) & 3) * STAGE_STRIDE;
#pragma unroll
            for (int i = 0; i < 2; i++) {
                cpa16(sb + doff[i],         pAh + k0 + i * 8);
                cpa16(sb + 16384 + doff[i], pAl + k0 + i * 8);
                cpa16(sb + 32768 + doff[i], pB  + k0 + i * 8);
            }
        }
        CPA_COMMIT();
        CPA_WAIT2();
        __syncthreads();

        uint32_t sA_H = sbase + (c & 3) * STAGE_STRIDE;
        uint32_t sA_L = sA_H + 16384, sB = sA_H + 32768;
#pragma unroll
        for (int kt = 0; kt < 4; kt++) {
            int kb = kt * 16;
            uint32_t ah[2][4], al[2][4];
#pragma unroll
            for (int mt = 0; mt < 2; mt++) {
                uint32_t off = SW128((uint32_t)((wm + mt * 16 + a_r) * 128 + (kb + a_k8) * 2));
                ldm4(sA_H + off, ah[mt]);
                ldm4(sA_L + off, al[mt]);
            }
#pragma unroll
            for (int ng = 0; ng < 2; ng++) {
                uint32_t boff = SW128((uint32_t)((wn + ng * 16 + b_n) * 128 + (kb + b_k8) * 2));
                uint32_t b4[4];
                ldm4(sB + boff, b4);
#pragma unroll
                for (int mt = 0; mt < 2; mt++) {
                    mma16816(acc[mt][2 * ng],     ah[mt], b4[0], b4[1]);
                    mma16816(acc[mt][2 * ng + 1], ah[mt], b4[2], b4[3]);
                    mma16816(acc[mt][2 * ng],     al[mt], b4[0], b4[1]);
                    mma16816(acc[mt][2 * ng + 1], al[mt], b4[2], b4[3]);
                }
            }
        }
    }

    // epilogue
#pragma unroll
    for (int mt = 0; mt < 2; mt++) {
        int r0 = m0 + wm + mt * 16 + (lane >> 2);
#pragma unroll
        for (int nt = 0; nt < 4; nt++) {
            int col = n0 + wn + nt * 8 + (lane & 3) * 2;
#pragma unroll
            for (int h = 0; h < 2; h++) {
                int row = r0 + h * 8;
                float v0 = acc[mt][nt][h * 2], v1 = acc[mt][nt][h * 2 + 1];
                if (g.Bv) { v0 += g.Bv[col]; v1 += g.Bv[col + 1]; }
                if (g.act == 1)      { v0 = fmaxf(v0, 0.f); v1 = fmaxf(v1, 0.f); }
                else if (g.act == 2) { v0 = geluf(v0); v1 = geluf(v1); }
                if (g.res) {
                    v0 += g.res[(size_t)row * DIM + col];
                    v1 += g.res[(size_t)row * DIM + col + 1];
                }
                v0 *= g.scale; v1 *= g.scale;
                size_t p = (size_t)row * DIM + col;
                *(float2*)(g.out + p) = make_float2(v0, v1);
                if (g.oh) {
                    __half h0, l0, h1, l1;
                    split_h(v0, h0, l0); split_h(v1, h1, l1);
                    *(uint32_t*)(g.oh + p) =
                        (uint32_t)__half_as_ushort(h0) | ((uint32_t)__half_as_ushort(h1) << 16);
                    *(uint32_t*)(g.ol + p) =
                        (uint32_t)__half_as_ushort(l0) | ((uint32_t)__half_as_ushort(l1) << 16);
                }
            }
        }
    }
}

// ---------------------------------------------------------------------------
// Flash attention (act0): O = softmax(QK^T/8) V  -> NX0 hi/lo
// grid (8, 32), 256 thr (8 warps), warp w owns rows w*16..w*16+15
// smem: Qh 16K | Ql 16K | K 8K | V 8K = 48KB
// ---------------------------------------------------------------------------
__global__ void __launch_bounds__(256) flash_k(int node) {
    if (g_nr[node].act != 0) return;
    extern __shared__ char smem[];
    uint32_t sQ_H = smem_u32(smem);
    uint32_t sQ_L = sQ_H + 16384;
    uint32_t sK = sQ_H + 32768, sV = sQ_H + 40960;

    int t = threadIdx.x, lane = t & 31, wid = t >> 5;
    int bh = blockIdx.y, b = bh >> 3, head = bh & 7;
    int i0 = blockIdx.x * 128;

    const float* Q = g_h0 + (size_t)b * SLEN * DIM + head * DH;
    const float* K = g_h1 + (size_t)b * SLEN * DIM + head * DH;
    const float* V = g_h2 + (size_t)b * SLEN * DIM + head * DH;

    {
        int lrow = t >> 1, lcb = (t & 1) * 32;
        const float* qr = Q + (size_t)(i0 + lrow) * DIM + lcb;
#pragma unroll
        for (int i = 0; i < 8; i++) {
            uint2 hi, lo; cvt_hilo(*(const float4*)(qr + i * 4), hi, lo);
            uint32_t off = SW128((uint32_t)(lrow * 128 + (lcb + i * 4) * 2));
            *(uint2*)(smem + off) = hi;
            *(uint2*)(smem + 16384 + off) = lo;
        }
    }

    float O[8][4];
#pragma unroll
    for (int d = 0; d < 8; d++)
#pragma unroll
        for (int l = 0; l < 4; l++) O[d][l] = 0.f;
    float mrow[2] = {-3.4e38f, -3.4e38f};
    float lrow_[2] = {0.f, 0.f};

    int a_r = (lane & 15), a_k8 = (lane >> 4) << 3;
    int b_n = ((lane & 16) >> 1) + (lane & 7), b_k8 = (lane & 8);
    int v_k = (lane & 15), v_n8 = (lane & 16) >> 1;
    int kvrow = t >> 2, kvcb = (t & 3) * 16;

    for (int jc = 0; jc < 16; jc++) {
        int j0 = jc * 64;
        {
            const float* kr = K + (size_t)(j0 + kvrow) * DIM + kvcb;
            const float* vr = V + (size_t)(j0 + kvrow) * DIM + kvcb;
#pragma unroll
            for (int i = 0; i < 4; i++) {
                uint32_t off = SW128((uint32_t)(kvrow * 128 + (kvcb + i * 4) * 2));
                *(uint2*)(smem + 32768 + off) = cvt_h(*(const float4*)(kr + i * 4));
                *(uint2*)(smem + 40960 + off) = cvt_h(*(const float4*)(vr + i * 4));
            }
        }
        __syncthreads();

        float s[8][4];
#pragma unroll
        for (int j = 0; j < 8; j++)
#pragma unroll
            for (int l = 0; l < 4; l++) s[j][l] = 0.f;
#pragma unroll
        for (int kt = 0; kt < 4; kt++) {
            int kb = kt * 16;
            uint32_t qh[4], ql[4];
            uint32_t qoff = SW128((uint32_t)((wid * 16 + a_r) * 128 + (kb + a_k8) * 2));
            ldm4(sQ_H + qoff, qh);
            ldm4(sQ_L + qoff, ql);
#pragma unroll
            for (int ng = 0; ng < 4; ng++) {
                uint32_t boff = SW128((uint32_t)((ng * 16 + b_n) * 128 + (kb + b_k8) * 2));
                uint32_t k4[4];
                ldm4(sK + boff, k4);
                mma16816(s[2 * ng],     qh, k4[0], k4[1]);
                mma16816(s[2 * ng + 1], qh, k4[2], k4[3]);
                mma16816(s[2 * ng],     ql, k4[0], k4[1]);
                mma16816(s[2 * ng + 1], ql, k4[2], k4[3]);
            }
        }
#pragma unroll
        for (int j = 0; j < 8; j++)
#pragma unroll
            for (int l = 0; l < 4; l++) s[j][l] *= 0.125f;

#pragma unroll
        for (int h = 0; h < 2; h++) {
            float mj = -3.4e38f;
#pragma unroll
            for (int j = 0; j < 8; j++) mj = fmaxf(mj, fmaxf(s[j][h * 2], s[j][h * 2 + 1]));
            mj = fmaxf(mj, __shfl_xor_sync(0xffffffffu, mj, 1));
            mj = fmaxf(mj, __shfl_xor_sync(0xffffffffu, mj, 2));
            float mnew = fmaxf(mrow[h], mj);
            float alpha = expf(mrow[h] - mnew);
            float ps = 0.f;
#pragma unroll
            for (int j = 0; j < 8; j++) {
                s[j][h * 2]     = expf(s[j][h * 2] - mnew);
                s[j][h * 2 + 1] = expf(s[j][h * 2 + 1] - mnew);
                ps += s[j][h * 2] + s[j][h * 2 + 1];
            }
            ps += __shfl_xor_sync(0xffffffffu, ps, 1);
            ps += __shfl_xor_sync(0xffffffffu, ps, 2);
            lrow_[h] = lrow_[h] * alpha + ps;
            mrow[h] = mnew;
#pragma unroll
            for (int d = 0; d < 8; d++) {
                O[d][h * 2]     *= alpha;
                O[d][h * 2 + 1] *= alpha;
            }
        }

#pragma unroll
        for (int g4 = 0; g4 < 4; g4++) {
            uint32_t ah[4], al[4];
            {
                uint2 hi, lo;
                cvt_hilo(make_float4(s[2 * g4][0], s[2 * g4][1], s[2 * g4][2], s[2 * g4][3]), hi, lo);
                ah[0] = hi.x; ah[1] = hi.y; al[0] = lo.x; al[1] = lo.y;
                cvt_hilo(make_float4(s[2 * g4 + 1][0], s[2 * g4 + 1][1], s[2 * g4 + 1][2], s[2 * g4 + 1][3]), hi, lo);
                ah[2] = hi.x; ah[3] = hi.y; al[2] = lo.x; al[3] = lo.y;
            }
            int kb = g4 * 16;
#pragma unroll
            for (int ng = 0; ng < 4; ng++) {
                uint32_t boff = SW128((uint32_t)((kb + v_k) * 128 + (ng * 16 + v_n8) * 2));
                uint32_t v4[4];
                ldm4t(sV + boff, v4);
                mma16816(O[2 * ng],     ah, v4[0], v4[1]);
                mma16816(O[2 * ng + 1], ah, v4[2], v4[3]);
                mma16816(O[2 * ng],     al, v4[0], v4[1]);
                mma16816(O[2 * ng + 1], al, v4[2], v4[3]);
            }
        }
        __syncthreads();
    }

    float inv0 = 1.0f / lrow_[0], inv1 = 1.0f / lrow_[1];
    __half* Oh = g_NXh + ((size_t)b * SLEN) * DIM + head * DH;
    __half* Ol = g_NXl + ((size_t)b * SLEN) * DIM + head * DH;
    int r0 = i0 + wid * 16 + (lane >> 2);
#pragma unroll
    for (int d = 0; d < 8; d++) {
        int col = d * 8 + (lane & 3) * 2;
#pragma unroll
        for (int h = 0; h < 2; h++) {
            int row = r0 + h * 8;
            float inv = h ? inv1 : inv0;
            float v0 = O[d][h * 2] * inv, v1 = O[d][h * 2 + 1] * inv;
            __half h0, l0, h1, l1;
            split_h(v0, h0, l0); split_h(v1, h1, l1);
            size_t p = (size_t)row * DIM + col;
            *(uint32_t*)(Oh + p) =
                (uint32_t)__half_as_ushort(h0) | ((uint32_t)__half_as_ushort(h1) << 16);
            *(uint32_t*)(Ol + p) =
                (uint32_t)__half_as_ushort(l0) | ((uint32_t)__half_as_ushort(l1) << 16);
        }
    }
}

// ---------------------------------------------------------------------------
// post_k: fused combine (acts 1,3 -> NX0 hi/lo) + finish (acts 2,4,5,6,7).
// warp-per-row, float4 ; grid 512
// ---------------------------------------------------------------------------
__global__ void post_k(int node) {
    NR r = g_nr[node];
    int a = r.act;
    if (a == 0) return;
    int warp = threadIdx.x >> 5, lane = threadIdx.x & 31;
    int row = blockIdx.x * 8 + warp;
    size_t rb = (size_t)row * DIM;
    int c0 = lane * 4;

    if (a == 1 || a == 3) {
#pragma unroll
        for (int i = 0; i < 4; i++) {
            size_t p = rb + c0 + i * 128;
            float4 a4 = *(const float4*)(g_h0 + p);
            float4 b4 = *(const float4*)(g_h1 + p);
            float4 y4;
            if (a == 1) {
                y4 = make_float4(a4.x * b4.x, a4.y * b4.y, a4.z * b4.z, a4.w * b4.w);
            } else {
                float4 cc4 = *(const float4*)(g_h2 + p);
                y4 = make_float4(fmaxf(a4.x + b4.x + cc4.x, 0.f), fmaxf(a4.y + b4.y + cc4.y, 0.f),
                                 fmaxf(a4.z + b4.z + cc4.z, 0.f), fmaxf(a4.w + b4.w + cc4.w, 0.f));
            }
            uint2 hi, lo; cvt_hilo(y4, hi, lo);
            *(uint2*)(g_NXh + p) = hi;
            *(uint2*)(g_NXl + p) = lo;
        }
        return;
    }

    float* out = g_outs + (size_t)node * MS + rb;
    if (a == 4 || a == 5 || a == 6) {
#pragma unroll
        for (int i = 0; i < 4; i++) {
            size_t p = rb + c0 + i * 128;
            float4 q4 = *(const float4*)(g_qv + p);
            float4 y4;
            if (a == 4) {
                float4 k4 = *(const float4*)(g_kv + p);
                float4 v4 = *(const float4*)(g_vv + p);
                y4 = make_float4(q4.x * sigmoidf_(k4.x) + v4.x, q4.y * sigmoidf_(k4.y) + v4.y,
                                 q4.z * sigmoidf_(k4.z) + v4.z, q4.w * sigmoidf_(k4.w) + v4.w);
            } else if (a == 5) {
                float4 h4 = *(const float4*)(g_h1 + p);
                y4 = make_float4(q4.x + h4.x, q4.y + h4.y, q4.z + h4.z, q4.w + h4.w);
            } else {
                float4 k4 = *(const float4*)(g_kv + p);
                y4 = make_float4(q4.x + k4.x, q4.y + k4.y, q4.z + k4.z, q4.w + k4.w);
            }
            *(float4*)(out + c0 + i * 128) =
                make_float4(r.aw * y4.x, r.aw * y4.y, r.aw * y4.z, r.aw * y4.w);
        }
        return;
    }
    // a == 2 or 7: LN
    float4 v4[4];
#pragma unroll
    for (int i = 0; i < 4; i++) {
        size_t p = rb + c0 + i * 128;
        float4 q4 = *(const float4*)(g_qv + p);
        if (a == 2) {
            float4 k4 = *(const float4*)(g_kv + p);
            float4 w4 = *(const float4*)(g_vv + p);
            v4[i] = make_float4(q4.x + k4.x + w4.x, q4.y + k4.y + w4.y,
                                q4.z + k4.z + w4.z, q4.w + k4.w + w4.w);
        } else {
            v4[i] = q4;
        }
    }
    float s = 0.f;
#pragma unroll
    for (int i = 0; i < 4; i++) s += v4[i].x + v4[i].y + v4[i].z + v4[i].w;
    float mean = wsum(s) * (1.0f / 512.0f);
    float q = 0.f;
#pragma unroll
    for (int i = 0; i < 4; i++) {
        float dx = v4[i].x - mean, dy = v4[i].y - mean, dz = v4[i].z - mean, dw = v4[i].w - mean;
        q += dx * dx + dy * dy + dz * dz + dw * dw;
    }
    float inv = rsqrtf(wsum(q) * (1.0f / 512.0f) + EPSLN);
    const float* gm = g_ptrs.node_g + node * DIM;
    const float* bt = g_ptrs.node_beta + node * DIM;
#pragma unroll
    for (int i = 0; i < 4; i++) {
        float4 g4 = *(const float4*)(gm + c0 + i * 128);
        float4 b4 = *(const float4*)(bt + c0 + i * 128);
        *(float4*)(out + c0 + i * 128) = make_float4(
            r.aw * ((v4[i].x - mean) * inv * g4.x + b4.x),
            r.aw * ((v4[i].y - mean) * inv * g4.y + b4.y),
            r.aw * ((v4[i].z - mean) * inv * g4.z + b4.z),
            r.aw * ((v4[i].w - mean) * inv * g4.w + b4.w));
    }
}

// final: sum unprocessed + LN ; warp-per-row, float4 ; grid 512
__global__ void final_k(float* dout) {
    int warp = threadIdx.x >> 5, lane = threadIdx.x & 31;
    int row = blockIdx.x * 8 + warp;
    size_t rb = (size_t)row * DIM;
    int c0 = lane * 4;
    float4 v4[4];
#pragma unroll
    for (int i = 0; i < 4; i++) v4[i] = make_float4(0.f, 0.f, 0.f, 0.f);
    for (int c = 0; c < 8; c++) {
        if (!g_processed[c]) {
            const float* o = g_outs + (size_t)c * MS + rb;
#pragma unroll
            for (int i = 0; i < 4; i++) {
                float4 t4 = *(const float4*)(o + c0 + i * 128);
                v4[i].x += t4.x; v4[i].y += t4.y; v4[i].z += t4.z; v4[i].w += t4.w;
            }
        }
    }
    float s = 0.f;
#pragma unroll
    for (int i = 0; i < 4; i++) s += v4[i].x + v4[i].y + v4[i].z + v4[i].w;
    float mean = wsum(s) * (1.0f / 512.0f);
    float q = 0.f;
#pragma unroll
    for (int i = 0; i < 4; i++) {
        float dx = v4[i].x - mean, dy = v4[i].y - mean, dz = v4[i].z - mean, dw = v4[i].w - mean;
        q += dx * dx + dy * dy + dz * dz + dw * dw;
    }
    float inv = rsqrtf(wsum(q) * (1.0f / 512.0f) + EPSLN);
#pragma unroll
    for (int i = 0; i < 4; i++) {
        float4 g4 = *(const float4*)(g_ptrs.out_g + c0 + i * 128);
        float4 b4 = *(const float4*)(g_ptrs.out_beta + c0 + i * 128);
        *(float4*)(dout + rb + c0 + i * 128) = make_float4(
            (v4[i].x - mean) * inv * g4.x + b4.x,
            (v4[i].y - mean) * inv * g4.y + b4.y,
            (v4[i].z - mean) * inv * g4.z + b4.z,
            (v4[i].w - mean) * inv * g4.w + b4.w);
    }
}

// ---------------------------------------------------------------------------
// Launch
// ---------------------------------------------------------------------------
extern "C" void kernel_launch(void* const* d_in, const int* in_sizes, int n_in,
                              void* d_out, int out_size) {
    (void)in_sizes; (void)n_in; (void)out_size;
    cudaFuncSetAttribute(gemm_mma, cudaFuncAttributeMaxDynamicSharedMemorySize, GEMM_SMEM);
    cudaFuncSetAttribute(flash_k,  cudaFuncAttributeMaxDynamicSharedMemorySize, 49152);

    setup_k<<<1, 1>>>(
        (const float*)d_in[0],  (const float*)d_in[1],  (const float*)d_in[2],
        (const float*)d_in[3],  (const float*)d_in[4],  (const float*)d_in[5],
        (const float*)d_in[6],  (const float*)d_in[7],  (const float*)d_in[8],
        (const float*)d_in[9],  (const float*)d_in[10], (const float*)d_in[11],
        (const float*)d_in[12], (const float*)d_in[13]);
    routing_k<<<1, 1>>>();
    conv_w_all<<<dim3(16, 16, 56), dim3(32, 8)>>>();

    for (int c = 0; c < 8; c++) {
        edge_pre<<<dim3(256, 3), 256>>>(c);
        gemm_mma<<<dim3(4, 32, 3), 512, GEMM_SMEM>>>(c, 0);   // edge q/k/v
        node_prep<<<512, 256>>>(c);
        gemm_mma<<<dim3(4, 32, 3), 512, GEMM_SMEM>>>(c, 3);   // node j0/j1/j2
        flash_k<<<dim3(8, 32), 256, 49152>>>(c);
        post_k<<<512, 256>>>(c);                              // combine + finish
        gemm_mma<<<dim3(4, 32, 1), 512, GEMM_SMEM>>>(c, 6);   // node j3
    }
    final_k<<<512, 256>>>((float*)d_out);
}